// round 1
// baseline (speedup 1.0000x reference)
#include <cuda_runtime.h>

#define NN 10000
#define EE 640000
#define DD 128
#define ALPHAF 0.2f
#define EPSF 1e-5f

// ---------------- device scratch (no allocation allowed) ----------------
__device__ float g_hlin[NN * DD];   // h @ W^T
__device__ int   g_cnt[NN];         // per-node in-degree
__device__ int   g_offs[NN + 1];    // CSR offsets (by destination row)
__device__ int   g_cur[NN];         // scatter cursors
__device__ int   g_cols[EE];        // permuted source node ids
__device__ float g_ws[EE];          // permuted edge weights

// ---------------- K0: zero counters ----------------
__global__ void k_zero() {
    int i = blockIdx.x * blockDim.x + threadIdx.x;
    if (i < NN) g_cnt[i] = 0;
}

// ---------------- K1: GEMM h_lin = h @ W^T ----------------
// Block: 256 threads, 64 rows x 128 cols of output.
// Shared: W transposed (d-major) 64KB + h tile 64x132 (padded) ~33KB.
__global__ void k_gemm(const float* __restrict__ h, const float* __restrict__ W, int n) {
    extern __shared__ float sm[];
    float* sWt = sm;                 // [128 d][128 k], d-major
    float* sH  = sm + 128 * 128;     // [64 r][132] padded
    const int HS = 132;
    int t  = threadIdx.x;
    int r0 = blockIdx.x * 64;

    // load W transposed: thread t -> row k = t/2, d-half = (t&1)*64
    {
        int k = t >> 1;
        int dbase = (t & 1) * 64;
        const float4* wrow = (const float4*)(W + k * 128 + dbase);
#pragma unroll
        for (int ii = 0; ii < 16; ++ii) {
            float4 v = wrow[ii];
            int d = dbase + ii * 4;
            sWt[(d + 0) * 128 + k] = v.x;
            sWt[(d + 1) * 128 + k] = v.y;
            sWt[(d + 2) * 128 + k] = v.z;
            sWt[(d + 3) * 128 + k] = v.w;
        }
    }
    // load h tile: thread t -> row t/4, 8 float4s
    {
        int rr = t >> 2;
        int c0 = (t & 3);
#pragma unroll
        for (int ii = 0; ii < 8; ++ii) {
            int c = c0 + ii * 4;           // float4 index 0..31
            int gr = r0 + rr;
            float4 v = make_float4(0.f, 0.f, 0.f, 0.f);
            if (gr < n) v = ((const float4*)(h + (size_t)gr * 128))[c];
            *(float4*)&sH[rr * HS + c * 4] = v;
        }
    }
    __syncthreads();

    int tx = t & 15;   // k = tx + 16*j
    int ty = t >> 4;   // rows ty + 16*i
    float acc[4][8];
#pragma unroll
    for (int i = 0; i < 4; ++i)
#pragma unroll
        for (int j = 0; j < 8; ++j) acc[i][j] = 0.f;

#pragma unroll 4
    for (int d = 0; d < 128; ++d) {
        float hv[4];
#pragma unroll
        for (int i = 0; i < 4; ++i) hv[i] = sH[(ty + 16 * i) * HS + d];
        float wv[8];
#pragma unroll
        for (int j = 0; j < 8; ++j) wv[j] = sWt[d * 128 + tx + 16 * j];
#pragma unroll
        for (int i = 0; i < 4; ++i)
#pragma unroll
            for (int j = 0; j < 8; ++j) acc[i][j] = fmaf(hv[i], wv[j], acc[i][j]);
    }

#pragma unroll
    for (int i = 0; i < 4; ++i) {
        int row = r0 + ty + 16 * i;
        if (row < n) {
#pragma unroll
            for (int j = 0; j < 8; ++j)
                g_hlin[(size_t)row * 128 + tx + 16 * j] = acc[i][j];
        }
    }
}

// ---------------- K2: histogram of destination rows ----------------
__global__ void k_hist(const int* __restrict__ row) {
    int e = blockIdx.x * blockDim.x + threadIdx.x;
    if (e < EE) atomicAdd(&g_cnt[row[e]], 1);
}

// ---------------- K3: single-block exclusive scan (10000 elems) ----------------
__global__ void k_scan() {
    const int T = 1024, C = 10;
    __shared__ int ps[T];
    int t = threadIdx.x;
    int base = t * C;
    int local[C];
    int s = 0;
#pragma unroll
    for (int j = 0; j < C; ++j) {
        int idx = base + j;
        int v = (idx < NN) ? g_cnt[idx] : 0;
        local[j] = s;
        s += v;
    }
    ps[t] = s;
    __syncthreads();
    for (int off = 1; off < T; off <<= 1) {
        int v = (t >= off) ? ps[t - off] : 0;
        __syncthreads();
        ps[t] += v;
        __syncthreads();
    }
    int pre = (t == 0) ? 0 : ps[t - 1];
#pragma unroll
    for (int j = 0; j < C; ++j) {
        int idx = base + j;
        if (idx < NN) {
            int o = pre + local[j];
            g_offs[idx] = o;
            g_cur[idx] = o;
        }
    }
    if (t == T - 1) g_offs[NN] = ps[T - 1];
}

// ---------------- K4: scatter edges into row-sorted order ----------------
__global__ void k_scatter(const int* __restrict__ row, const int* __restrict__ col,
                          const float* __restrict__ w) {
    int e = blockIdx.x * blockDim.x + threadIdx.x;
    if (e < EE) {
        int r = row[e];
        int pos = atomicAdd(&g_cur[r], 1);
        g_cols[pos] = col[e];
        g_ws[pos]   = w[e];
    }
}

// ---------------- K5: per-node aggregate + LayerNorm + ReLU + residual ----------------
// One warp per node; each lane owns 4 consecutive features (float4).
__global__ void k_agg(const float* __restrict__ h0, const float* __restrict__ gamma,
                      const float* __restrict__ beta, float* __restrict__ out) {
    int wid  = threadIdx.x >> 5;
    int lane = threadIdx.x & 31;
    int node = blockIdx.x * 8 + wid;
    if (node >= NN) return;

    int beg = g_offs[node];
    int end = g_offs[node + 1];
    const float4* HL = (const float4*)g_hlin;

    float4 a0 = make_float4(0.f, 0.f, 0.f, 0.f);
    float4 a1 = a0, a2 = a0, a3 = a0;

    int i = beg;
    for (; i + 4 <= end; i += 4) {
        int c0 = g_cols[i],     c1 = g_cols[i + 1];
        int c2 = g_cols[i + 2], c3 = g_cols[i + 3];
        float w0 = g_ws[i],     w1 = g_ws[i + 1];
        float w2 = g_ws[i + 2], w3 = g_ws[i + 3];
        float4 v0 = HL[c0 * 32 + lane];
        float4 v1 = HL[c1 * 32 + lane];
        float4 v2 = HL[c2 * 32 + lane];
        float4 v3 = HL[c3 * 32 + lane];
        a0.x = fmaf(w0, v0.x, a0.x); a0.y = fmaf(w0, v0.y, a0.y);
        a0.z = fmaf(w0, v0.z, a0.z); a0.w = fmaf(w0, v0.w, a0.w);
        a1.x = fmaf(w1, v1.x, a1.x); a1.y = fmaf(w1, v1.y, a1.y);
        a1.z = fmaf(w1, v1.z, a1.z); a1.w = fmaf(w1, v1.w, a1.w);
        a2.x = fmaf(w2, v2.x, a2.x); a2.y = fmaf(w2, v2.y, a2.y);
        a2.z = fmaf(w2, v2.z, a2.z); a2.w = fmaf(w2, v2.w, a2.w);
        a3.x = fmaf(w3, v3.x, a3.x); a3.y = fmaf(w3, v3.y, a3.y);
        a3.z = fmaf(w3, v3.z, a3.z); a3.w = fmaf(w3, v3.w, a3.w);
    }
    for (; i < end; ++i) {
        int c = g_cols[i];
        float w = g_ws[i];
        float4 v = HL[c * 32 + lane];
        a0.x = fmaf(w, v.x, a0.x); a0.y = fmaf(w, v.y, a0.y);
        a0.z = fmaf(w, v.z, a0.z); a0.w = fmaf(w, v.w, a0.w);
    }

    float4 x;
    x.x = a0.x + a1.x + a2.x + a3.x;
    x.y = a0.y + a1.y + a2.y + a3.y;
    x.z = a0.z + a1.z + a2.z + a3.z;
    x.w = a0.w + a1.w + a2.w + a3.w;

    float s1 = x.x + x.y + x.z + x.w;
    float s2 = x.x * x.x + x.y * x.y + x.z * x.z + x.w * x.w;
#pragma unroll
    for (int off = 16; off; off >>= 1) {
        s1 += __shfl_xor_sync(0xffffffffu, s1, off);
        s2 += __shfl_xor_sync(0xffffffffu, s2, off);
    }
    float mu  = s1 * (1.0f / 128.0f);
    float var = s2 * (1.0f / 128.0f) - mu * mu;
    float rs  = rsqrtf(var + EPSF);

    float4 g  = ((const float4*)gamma)[lane];
    float4 b  = ((const float4*)beta)[lane];
    float4 r0 = ((const float4*)(h0 + (size_t)node * DD))[lane];

    float4 y;
    y.x = fmaxf(0.f, (x.x - mu) * rs * g.x + b.x) * (1.f - ALPHAF) + ALPHAF * r0.x;
    y.y = fmaxf(0.f, (x.y - mu) * rs * g.y + b.y) * (1.f - ALPHAF) + ALPHAF * r0.y;
    y.z = fmaxf(0.f, (x.z - mu) * rs * g.z + b.z) * (1.f - ALPHAF) + ALPHAF * r0.z;
    y.w = fmaxf(0.f, (x.w - mu) * rs * g.w + b.w) * (1.f - ALPHAF) + ALPHAF * r0.w;

    ((float4*)(out + (size_t)node * DD))[lane] = y;
}

// ---------------- launch ----------------
extern "C" void kernel_launch(void* const* d_in, const int* in_sizes, int n_in,
                              void* d_out, int out_size) {
    const float* h     = (const float*)d_in[0];
    const float* h0    = (const float*)d_in[1];
    const float* nw    = (const float*)d_in[2];
    const float* W     = (const float*)d_in[3];
    const float* gamma = (const float*)d_in[4];
    const float* beta  = (const float*)d_in[5];
    const int*   row   = (const int*)d_in[6];
    const int*   col   = (const int*)d_in[7];
    float* out = (float*)d_out;

    size_t smem = (size_t)(128 * 128 + 64 * 132) * sizeof(float);  // ~97.8 KB
    cudaFuncSetAttribute(k_gemm, cudaFuncAttributeMaxDynamicSharedMemorySize, (int)smem);

    k_zero<<<(NN + 255) / 256, 256>>>();
    k_gemm<<<(NN + 63) / 64, 256, smem>>>(h, W, NN);
    k_hist<<<(EE + 255) / 256, 256>>>(row);
    k_scan<<<1, 1024>>>();
    k_scatter<<<(EE + 255) / 256, 256>>>(row, col, nw);
    k_agg<<<(NN + 7) / 8, 256>>>(h0, gamma, beta, out);
}

// round 2
// speedup vs baseline: 1.4536x; 1.4536x over previous
#include <cuda_runtime.h>
#include <cuda_fp16.h>

#define NN 10000
#define EE 640000
#define DD 128
#define SLOT 160
#define ALPHAF 0.2f
#define EPSF 1e-5f

// ---------------- device scratch (no allocation allowed) ----------------
__device__ __half g_hlin[NN * DD];          // h @ W^T, fp16
__device__ int    g_cnt[NN];                // per-node in-degree / cursor
__device__ int2   g_bkt[(size_t)NN * SLOT]; // (col, bitcast(w)) per dest-node bucket

// ---------------- K1: GEMM h_lin = h @ W^T (+ zero counters) ----------------
// Block: 256 threads, 64 rows x 128 cols of output.
__global__ void k_gemm(const float* __restrict__ h, const float* __restrict__ W, int n) {
    extern __shared__ float sm[];
    float* sWt = sm;                 // [128 d][128 k], d-major
    float* sH  = sm + 128 * 128;     // [64 r][132] padded
    const int HS = 132;
    int t  = threadIdx.x;
    int r0 = blockIdx.x * 64;

    // fold: zero bucket counters (grid covers NN; next kernel depends on this one)
    {
        int gi = blockIdx.x * 256 + t;
        if (gi < NN) g_cnt[gi] = 0;
    }

    // load W transposed: thread t -> row k = t/2, d-half = (t&1)*64
    {
        int k = t >> 1;
        int dbase = (t & 1) * 64;
        const float4* wrow = (const float4*)(W + k * 128 + dbase);
#pragma unroll
        for (int ii = 0; ii < 16; ++ii) {
            float4 v = wrow[ii];
            int d = dbase + ii * 4;
            sWt[(d + 0) * 128 + k] = v.x;
            sWt[(d + 1) * 128 + k] = v.y;
            sWt[(d + 2) * 128 + k] = v.z;
            sWt[(d + 3) * 128 + k] = v.w;
        }
    }
    // load h tile: thread t -> row t/4, 8 float4s
    {
        int rr = t >> 2;
        int c0 = (t & 3);
#pragma unroll
        for (int ii = 0; ii < 8; ++ii) {
            int c = c0 + ii * 4;
            int gr = r0 + rr;
            float4 v = make_float4(0.f, 0.f, 0.f, 0.f);
            if (gr < n) v = ((const float4*)(h + (size_t)gr * 128))[c];
            *(float4*)&sH[rr * HS + c * 4] = v;
        }
    }
    __syncthreads();

    int tx = t & 15;   // col = tx + 16*j
    int ty = t >> 4;   // rows ty + 16*i
    float acc[4][8];
#pragma unroll
    for (int i = 0; i < 4; ++i)
#pragma unroll
        for (int j = 0; j < 8; ++j) acc[i][j] = 0.f;

#pragma unroll 4
    for (int d = 0; d < 128; ++d) {
        float hv[4];
#pragma unroll
        for (int i = 0; i < 4; ++i) hv[i] = sH[(ty + 16 * i) * HS + d];
        float wv[8];
#pragma unroll
        for (int j = 0; j < 8; ++j) wv[j] = sWt[d * 128 + tx + 16 * j];
#pragma unroll
        for (int i = 0; i < 4; ++i)
#pragma unroll
            for (int j = 0; j < 8; ++j) acc[i][j] = fmaf(hv[i], wv[j], acc[i][j]);
    }

#pragma unroll
    for (int i = 0; i < 4; ++i) {
        int row = r0 + ty + 16 * i;
        if (row < n) {
#pragma unroll
            for (int j = 0; j < 8; ++j)
                g_hlin[(size_t)row * 128 + tx + 16 * j] = __float2half_rn(acc[i][j]);
        }
    }
}

// ---------------- K2: bucket edges by destination (replaces hist+scan+scatter) ----------------
__global__ void k_bucket(const int* __restrict__ row, const int* __restrict__ col,
                         const float* __restrict__ w) {
    int e = blockIdx.x * blockDim.x + threadIdx.x;
    if (e < EE) {
        int r = row[e];
        int pos = atomicAdd(&g_cnt[r], 1);
        if (pos < SLOT)
            g_bkt[(size_t)r * SLOT + pos] = make_int2(col[e], __float_as_int(w[e]));
    }
}

// ---------------- K3: per-node aggregate + LayerNorm + ReLU + residual ----------------
// One warp per node; each lane owns 4 consecutive features (2x half2 = 8B gather).
__global__ void k_agg(const float* __restrict__ h0, const float* __restrict__ gamma,
                      const float* __restrict__ beta, float* __restrict__ out) {
    int wid  = threadIdx.x >> 5;
    int lane = threadIdx.x & 31;
    int node = blockIdx.x * 8 + wid;
    if (node >= NN) return;

    int cnt = g_cnt[node];
    if (cnt > SLOT) cnt = SLOT;
    const int2* bkt = g_bkt + (size_t)node * SLOT;
    const uint2* HL = (const uint2*)g_hlin;   // 32 uint2 per row

    float4 a0 = make_float4(0.f, 0.f, 0.f, 0.f);
    float4 a1 = a0, a2 = a0, a3 = a0;

    int i = 0;
    for (; i + 4 <= cnt; i += 4) {
        int2 e0 = bkt[i], e1 = bkt[i + 1], e2 = bkt[i + 2], e3 = bkt[i + 3];
        uint2 p0 = HL[(size_t)e0.x * 32 + lane];
        uint2 p1 = HL[(size_t)e1.x * 32 + lane];
        uint2 p2 = HL[(size_t)e2.x * 32 + lane];
        uint2 p3 = HL[(size_t)e3.x * 32 + lane];
        float w0 = __int_as_float(e0.y), w1 = __int_as_float(e1.y);
        float w2 = __int_as_float(e2.y), w3 = __int_as_float(e3.y);

        float2 f;
        f = __half22float2(*(__half2*)&p0.x); a0.x = fmaf(w0, f.x, a0.x); a0.y = fmaf(w0, f.y, a0.y);
        f = __half22float2(*(__half2*)&p0.y); a0.z = fmaf(w0, f.x, a0.z); a0.w = fmaf(w0, f.y, a0.w);
        f = __half22float2(*(__half2*)&p1.x); a1.x = fmaf(w1, f.x, a1.x); a1.y = fmaf(w1, f.y, a1.y);
        f = __half22float2(*(__half2*)&p1.y); a1.z = fmaf(w1, f.x, a1.z); a1.w = fmaf(w1, f.y, a1.w);
        f = __half22float2(*(__half2*)&p2.x); a2.x = fmaf(w2, f.x, a2.x); a2.y = fmaf(w2, f.y, a2.y);
        f = __half22float2(*(__half2*)&p2.y); a2.z = fmaf(w2, f.x, a2.z); a2.w = fmaf(w2, f.y, a2.w);
        f = __half22float2(*(__half2*)&p3.x); a3.x = fmaf(w3, f.x, a3.x); a3.y = fmaf(w3, f.y, a3.y);
        f = __half22float2(*(__half2*)&p3.y); a3.z = fmaf(w3, f.x, a3.z); a3.w = fmaf(w3, f.y, a3.w);
    }
    for (; i < cnt; ++i) {
        int2 e0 = bkt[i];
        uint2 p0 = HL[(size_t)e0.x * 32 + lane];
        float w0 = __int_as_float(e0.y);
        float2 f;
        f = __half22float2(*(__half2*)&p0.x); a0.x = fmaf(w0, f.x, a0.x); a0.y = fmaf(w0, f.y, a0.y);
        f = __half22float2(*(__half2*)&p0.y); a0.z = fmaf(w0, f.x, a0.z); a0.w = fmaf(w0, f.y, a0.w);
    }

    float4 x;
    x.x = (a0.x + a1.x) + (a2.x + a3.x);
    x.y = (a0.y + a1.y) + (a2.y + a3.y);
    x.z = (a0.z + a1.z) + (a2.z + a3.z);
    x.w = (a0.w + a1.w) + (a2.w + a3.w);

    float s1 = x.x + x.y + x.z + x.w;
    float s2 = x.x * x.x + x.y * x.y + x.z * x.z + x.w * x.w;
#pragma unroll
    for (int off = 16; off; off >>= 1) {
        s1 += __shfl_xor_sync(0xffffffffu, s1, off);
        s2 += __shfl_xor_sync(0xffffffffu, s2, off);
    }
    float mu  = s1 * (1.0f / 128.0f);
    float var = s2 * (1.0f / 128.0f) - mu * mu;
    float rs  = rsqrtf(var + EPSF);

    float4 g  = ((const float4*)gamma)[lane];
    float4 b  = ((const float4*)beta)[lane];
    float4 r0 = ((const float4*)(h0 + (size_t)node * DD))[lane];

    float4 y;
    y.x = fmaxf(0.f, (x.x - mu) * rs * g.x + b.x) * (1.f - ALPHAF) + ALPHAF * r0.x;
    y.y = fmaxf(0.f, (x.y - mu) * rs * g.y + b.y) * (1.f - ALPHAF) + ALPHAF * r0.y;
    y.z = fmaxf(0.f, (x.z - mu) * rs * g.z + b.z) * (1.f - ALPHAF) + ALPHAF * r0.z;
    y.w = fmaxf(0.f, (x.w - mu) * rs * g.w + b.w) * (1.f - ALPHAF) + ALPHAF * r0.w;

    ((float4*)(out + (size_t)node * DD))[lane] = y;
}

// ---------------- launch ----------------
extern "C" void kernel_launch(void* const* d_in, const int* in_sizes, int n_in,
                              void* d_out, int out_size) {
    const float* h     = (const float*)d_in[0];
    const float* h0    = (const float*)d_in[1];
    const float* nw    = (const float*)d_in[2];
    const float* W     = (const float*)d_in[3];
    const float* gamma = (const float*)d_in[4];
    const float* beta  = (const float*)d_in[5];
    const int*   row   = (const int*)d_in[6];
    const int*   col   = (const int*)d_in[7];
    float* out = (float*)d_out;

    size_t smem = (size_t)(128 * 128 + 64 * 132) * sizeof(float);  // ~97.8 KB
    cudaFuncSetAttribute(k_gemm, cudaFuncAttributeMaxDynamicSharedMemorySize, (int)smem);

    k_gemm<<<(NN + 63) / 64, 256, smem>>>(h, W, NN);
    k_bucket<<<(EE + 255) / 256, 256>>>(row, col, nw);
    k_agg<<<(NN + 7) / 8, 256>>>(h0, gamma, beta, out);
}